// round 16
// baseline (speedup 1.0000x reference)
#include <cuda_runtime.h>
#include <cuda_bf16.h>
#include <cuda_fp16.h>
#include <cstdint>

#define DIM 256
#define N_NODES_MAX 50000
#define N_EDGES_MAX 800000
#define ELLW 96              // ELL row width (avg degree 16; P(>96) ~ 0)
#define OVF_CAP 4096

// ----- scratch (__device__ globals; no cudaMalloc allowed) -----
__device__ __half  g_hidden_h[N_NODES_MAX * DIM];     // x @ W (fp16)
__device__ __half  g_WT[DIM * DIM];                   // W^T fp16 (WT[n][k])
__device__ int     g_counts[N_NODES_MAX];             // per-row edge counts
__device__ int2    g_ell[(size_t)N_NODES_MAX * ELLW]; // (col, val-bits) per slot
__device__ int     g_ovf_cnt[1];
__device__ int4    g_ovf[OVF_CAP];                    // (row, col, val-bits, _)

// ===========================================================================
// Kernel 0: W^T fp16.  WT[n][k] = W[k][n]
// ===========================================================================
__global__ void wt_convert_kernel(const float* __restrict__ W,
                                  __half* __restrict__ wt) {
    int k = blockIdx.x;
    int n = threadIdx.x;
    wt[n * DIM + k] = __float2half_rn(W[k * DIM + n]);
}

// ===========================================================================
// Kernel 1: mma.sync fp16 GEMM over an N half (n_base in 64-col blocks).
// Same body as the current passing kernel (KC=128, LDSM), grid(2, M/128).
// ===========================================================================
#define SA 136    // A smem row stride (128 + 8 pad) in halves
#define SB 264    // B smem row stride (256 + 8 pad) in halves
#define A_OFF 0
#define B_OFF (128 * SA)
#define GEMM_SMEM_BYTES ((128 * SA + 64 * SB) * 2)   // 68608

__device__ __forceinline__ void mma16816(float* c, const uint32_t* a, const uint32_t* b) {
    asm volatile(
        "mma.sync.aligned.m16n8k16.row.col.f32.f16.f16.f32 "
        "{%0,%1,%2,%3}, {%4,%5,%6,%7}, {%8,%9}, {%0,%1,%2,%3};"
        : "+f"(c[0]), "+f"(c[1]), "+f"(c[2]), "+f"(c[3])
        : "r"(a[0]), "r"(a[1]), "r"(a[2]), "r"(a[3]), "r"(b[0]), "r"(b[1]));
}

#define LDSM_X4(r0, r1, r2, r3, addr) \
    asm volatile("ldmatrix.sync.aligned.m8n8.x4.shared.b16 {%0,%1,%2,%3}, [%4];" \
                 : "=r"(r0), "=r"(r1), "=r"(r2), "=r"(r3) : "r"(addr))

__global__ __launch_bounds__(256, 2) void gemm_mma_kernel(
        const float* __restrict__ x,
        const __half* __restrict__ wt,
        __half* __restrict__ hidden, int M, int n_base) {
    extern __shared__ __half sm[];

    const int tid  = threadIdx.x;
    const int warp = tid >> 5;
    const int lane = tid & 31;
    const int gid  = lane >> 2;
    const int tig  = lane & 3;
    const int wm   = warp >> 1;
    const int wn   = warp & 1;
    const int blockM = blockIdx.y * 128;
    const int blockN = (blockIdx.x + n_base) * 64;

    // ---- load B tile (full K): 64 rows x 256 k ----
#pragma unroll
    for (int t = 0; t < 8; t++) {
        int idx = tid + t * 256;
        int n = idx >> 5;
        int j = idx & 31;
        *reinterpret_cast<uint4*>(&sm[B_OFF + n * SB + j * 8]) =
            *reinterpret_cast<const uint4*>(&wt[(size_t)(blockN + n) * DIM + j * 8]);
    }

    const uint32_t smem_u32 = (uint32_t)__cvta_generic_to_shared(sm);
    uint32_t aAddr[2];
#pragma unroll
    for (int f = 0; f < 2; f++)
        aAddr[f] = smem_u32 + 2u * (uint32_t)(A_OFF +
                     (wm * 32 + f * 16 + (lane & 15)) * SA + ((lane >> 4) << 3));
    uint32_t bAddr[2];
#pragma unroll
    for (int q = 0; q < 2; q++)
        bAddr[q] = smem_u32 + 2u * (uint32_t)(B_OFF +
                     (wn * 32 + q * 16 + (lane & 7) + ((lane >> 4) & 1) * 8) * SB +
                     ((lane >> 3) & 1) * 8);

    float c[2][4][4];
#pragma unroll
    for (int f = 0; f < 2; f++)
#pragma unroll
        for (int g = 0; g < 4; g++)
#pragma unroll
            for (int q = 0; q < 4; q++) c[f][g][q] = 0.f;

    for (int kc = 0; kc < 2; kc++) {          // two K=128 chunks
        __syncthreads();
#pragma unroll
        for (int t = 0; t < 16; t++) {
            int idx = tid + t * 256;
            int row = idx >> 5;
            int c4  = idx & 31;
            float4 v = make_float4(0.f, 0.f, 0.f, 0.f);
            if (blockM + row < M)
                v = *reinterpret_cast<const float4*>(
                        &x[(size_t)(blockM + row) * DIM + kc * 128 + c4 * 4]);
            __half2 p0 = __floats2half2_rn(v.x, v.y);
            __half2 p1 = __floats2half2_rn(v.z, v.w);
            *reinterpret_cast<uint2*>(&sm[A_OFF + row * SA + c4 * 4]) =
                make_uint2(*reinterpret_cast<uint32_t*>(&p0),
                           *reinterpret_cast<uint32_t*>(&p1));
        }
        __syncthreads();

#pragma unroll
        for (int ks = 0; ks < 8; ks++) {
            const int kb = ks * 16;
            uint32_t a[2][4], bb[4][2];
            LDSM_X4(a[0][0], a[0][1], a[0][2], a[0][3], aAddr[0] + 2 * kb);
            LDSM_X4(a[1][0], a[1][1], a[1][2], a[1][3], aAddr[1] + 2 * kb);
            LDSM_X4(bb[0][0], bb[0][1], bb[1][0], bb[1][1],
                    bAddr[0] + 2 * (kc * 128 + kb));
            LDSM_X4(bb[2][0], bb[2][1], bb[3][0], bb[3][1],
                    bAddr[1] + 2 * (kc * 128 + kb));
#pragma unroll
            for (int f = 0; f < 2; f++)
#pragma unroll
                for (int g = 0; g < 4; g++)
                    mma16816(c[f][g], a[f], bb[g]);
        }
    }

#pragma unroll
    for (int f = 0; f < 2; f++) {
#pragma unroll
        for (int g = 0; g < 4; g++) {
            int row = blockM + wm * 32 + f * 16 + gid;
            int col = blockN + wn * 32 + g * 8 + 2 * tig;
            if (row < M)
                *reinterpret_cast<__half2*>(&hidden[(size_t)row * DIM + col]) =
                    __floats2half2_rn(c[f][g][0], c[f][g][1]);
            if (row + 8 < M)
                *reinterpret_cast<__half2*>(&hidden[(size_t)(row + 8) * DIM + col]) =
                    __floats2half2_rn(c[f][g][2], c[f][g][3]);
        }
    }
}

// ===========================================================================
// ELL build: ONE scatter kernel.
// ===========================================================================
__global__ void ell_scatter_kernel(const int* __restrict__ rows,
                                   const int* __restrict__ cols,
                                   const float* __restrict__ vals,
                                   int*  __restrict__ counts,
                                   int2* __restrict__ ell,
                                   int*  __restrict__ ovf_cnt,
                                   int4* __restrict__ ovf,
                                   int E) {
    int i = blockIdx.x * blockDim.x + threadIdx.x;
    if (i < E) {
        int r   = rows[i];
        int pos = atomicAdd(&counts[r], 1);
        if (pos < ELLW) {
            ell[(size_t)r * ELLW + pos] = make_int2(cols[i], __float_as_int(vals[i]));
        } else {
            int o = atomicAdd(ovf_cnt, 1);
            if (o < OVF_CAP)
                ovf[o] = make_int4(r, cols[i], __float_as_int(vals[i]), 0);
        }
    }
}

// ===========================================================================
// SpMM over a 128-dim column half: warp per dest row, lane owns 4 dims
// (one LDG.64 gather per edge), 8-edge unroll.
// ===========================================================================
__device__ __forceinline__ void fma4_half(float* acc, uint2 r, float v) {
    float2 f0 = __half22float2(*reinterpret_cast<__half2*>(&r.x));
    float2 f1 = __half22float2(*reinterpret_cast<__half2*>(&r.y));
    acc[0] = fmaf(v, f0.x, acc[0]); acc[1] = fmaf(v, f0.y, acc[1]);
    acc[2] = fmaf(v, f1.x, acc[2]); acc[3] = fmaf(v, f1.y, acc[3]);
}

__global__ __launch_bounds__(256) void spmm_half_kernel(const int*  __restrict__ counts,
                                                        const int2* __restrict__ ell,
                                                        const __half* __restrict__ hidden,
                                                        const float* __restrict__ b,
                                                        float*       __restrict__ out,
                                                        int M, int colOff) {
    const int w    = (blockIdx.x * blockDim.x + threadIdx.x) >> 5;
    const int lane = threadIdx.x & 31;
    if (w >= M) return;

    const int cnt = min(counts[w], ELLW);
    const int2* erow = ell + (size_t)w * ELLW;

    float acc[4] = {0.f, 0.f, 0.f, 0.f};
    const __half* hbase = hidden + colOff + lane * 4;

    int j = 0;
    for (; j + 7 < cnt; j += 8) {
        int2 p[8];
#pragma unroll
        for (int q = 0; q < 8; q++) p[q] = erow[j + q];
        uint2 r[8];
#pragma unroll
        for (int q = 0; q < 8; q++)
            r[q] = *reinterpret_cast<const uint2*>(hbase + (size_t)p[q].x * DIM);
#pragma unroll
        for (int q = 0; q < 8; q++)
            fma4_half(acc, r[q], __int_as_float(p[q].y));
    }
    for (; j < cnt; j++) {
        int2 p0 = erow[j];
        uint2 r0 = *reinterpret_cast<const uint2*>(hbase + (size_t)p0.x * DIM);
        fma4_half(acc, r0, __int_as_float(p0.y));
    }

    float4 bb = *reinterpret_cast<const float4*>(b + colOff + lane * 4);
    *reinterpret_cast<float4*>(out + (size_t)w * DIM + colOff + lane * 4) =
        make_float4(acc[0] + bb.x, acc[1] + bb.y, acc[2] + bb.z, acc[3] + bb.w);
}

// ===========================================================================
// Overflow fixup: normally n==0.
// ===========================================================================
__global__ void ovf_fixup_kernel(const int* __restrict__ ovf_cnt,
                                 const int4* __restrict__ ovf,
                                 const __half* __restrict__ hidden,
                                 float* __restrict__ out) {
    int n = min(*ovf_cnt, OVF_CAP);
    int t = threadIdx.x;
    for (int e = 0; e < n; e++) {
        int4 p = ovf[e];
        float v = __int_as_float(p.z);
        out[(size_t)p.x * DIM + t] =
            fmaf(v, __half2float(hidden[(size_t)p.y * DIM + t]),
                 out[(size_t)p.x * DIM + t]);
    }
}

// ===========================================================================
// Launch — N-split pipeline (viable now that ELL build is ~20us):
//   s_csr  : memsets -> ell_scatter                    (done ~t=20)
//   default: wt -> gemm0(cols 0-127) -> gemm1(cols 128-255)
//   s_aux  : spmm0(cols 0-127)  [after gemm0 + ELL; overlaps gemm1]
//   default: spmm1(cols 128-255) [after gemm1 + ELL] -> [wait spmm0] fixup
// ===========================================================================
extern "C" void kernel_launch(void* const* d_in, const int* in_sizes, int n_in,
                              void* d_out, int out_size) {
    const float* x        = (const float*)d_in[0];
    const int*   adj_rows = (const int*)  d_in[1];
    const int*   adj_cols = (const int*)  d_in[2];
    const float* adj_vals = (const float*)d_in[3];
    const float* W        = (const float*)d_in[4];
    const float* b        = (const float*)d_in[5];
    float*       out      = (float*)d_out;

    const int M = in_sizes[0] / DIM;   // 50000
    const int E = in_sizes[1];         // 800000

    __half *hidden, *wt;
    int *counts, *ovf_cnt;
    int2 *ell;
    int4 *ovf;
    cudaGetSymbolAddress((void**)&hidden,  g_hidden_h);
    cudaGetSymbolAddress((void**)&wt,      g_WT);
    cudaGetSymbolAddress((void**)&counts,  g_counts);
    cudaGetSymbolAddress((void**)&ell,     g_ell);
    cudaGetSymbolAddress((void**)&ovf_cnt, g_ovf_cnt);
    cudaGetSymbolAddress((void**)&ovf,     g_ovf);

    static cudaStream_t s_csr = nullptr, s_aux = nullptr;
    static cudaEvent_t  ev_fork = nullptr, ev_csr = nullptr, ev_g0 = nullptr, ev_sp0 = nullptr;
    if (s_csr == nullptr) {
        cudaStreamCreateWithFlags(&s_csr, cudaStreamNonBlocking);
        cudaStreamCreateWithFlags(&s_aux, cudaStreamNonBlocking);
        cudaEventCreateWithFlags(&ev_fork, cudaEventDisableTiming);
        cudaEventCreateWithFlags(&ev_csr,  cudaEventDisableTiming);
        cudaEventCreateWithFlags(&ev_g0,   cudaEventDisableTiming);
        cudaEventCreateWithFlags(&ev_sp0,  cudaEventDisableTiming);
        cudaFuncSetAttribute(gemm_mma_kernel,
                             cudaFuncAttributeMaxDynamicSharedMemorySize, GEMM_SMEM_BYTES);
    }

    const int spmmBlocks = (M * 32 + 255) / 256;

    // ---- fork: ELL build on s_csr ----
    cudaEventRecord(ev_fork, 0);
    cudaStreamWaitEvent(s_csr, ev_fork, 0);

    cudaMemsetAsync(counts, 0, (size_t)M * sizeof(int), s_csr);
    cudaMemsetAsync(ovf_cnt, 0, sizeof(int), s_csr);
    ell_scatter_kernel<<<(E + 255) / 256, 256, 0, s_csr>>>(adj_rows, adj_cols, adj_vals,
                                                           counts, ell, ovf_cnt, ovf, E);
    cudaEventRecord(ev_csr, s_csr);

    // ---- GEMM half 0 (cols 0-127) ----
    wt_convert_kernel<<<DIM, DIM>>>(W, wt);
    dim3 gemmGrid(2, (M + 127) / 128);
    gemm_mma_kernel<<<gemmGrid, 256, GEMM_SMEM_BYTES>>>(x, wt, hidden, M, 0);
    cudaEventRecord(ev_g0, 0);

    // ---- GEMM half 1 (cols 128-255) on default ----
    gemm_mma_kernel<<<gemmGrid, 256, GEMM_SMEM_BYTES>>>(x, wt, hidden, M, 2);

    // ---- SpMM half 0 on s_aux: after gemm0 + ELL; overlaps gemm1 ----
    cudaStreamWaitEvent(s_aux, ev_g0, 0);
    cudaStreamWaitEvent(s_aux, ev_csr, 0);
    spmm_half_kernel<<<spmmBlocks, 256, 0, s_aux>>>(counts, ell, hidden, b, out, M, 0);
    cudaEventRecord(ev_sp0, s_aux);

    // ---- SpMM half 1 on default, then join + fixup ----
    cudaStreamWaitEvent(0, ev_csr, 0);
    spmm_half_kernel<<<spmmBlocks, 256>>>(counts, ell, hidden, b, out, M, 128);
    cudaStreamWaitEvent(0, ev_sp0, 0);
    ovf_fixup_kernel<<<1, 256>>>(ovf_cnt, ovf, hidden, out);
}